// round 7
// baseline (speedup 1.0000x reference)
#include <cuda_runtime.h>
#include <cuda_fp16.h>
#include <stdint.h>
#include <math.h>

#define N_FRAMES 2048
#define N_AGENTS 32
#define N_ROWS 65536
#define FEAT 512
#define HID 140
#define OUT2 256

#define OFF_A0 (N_ROWS * OUT2)
#define OFF_A1 (OFF_A0 + N_ROWS * 8)
#define OFF_A2 (OFF_A1 + N_ROWS * 6)

// padded dims
#define K1P 576   // 512 feat + 18 onehot + bias@530 + pad
#define N1P 144   // 140 hid + ones@140 + pad
#define K2P 144
#define KIP 1024  // cur|next
#define NIP 24

// single-fp16 transposed weights
__device__ __align__(16) __half g_w1t[N1P * K1P];     // [n][k]
__device__ __align__(16) __half g_wit[NIP * KIP];     // [n][k]
__device__ __align__(16) __half g_w2t[OUT2 * K2P];    // [n][k]

// ---------------------------------------------------------------- helpers
__device__ __forceinline__ uint32_t smaddr(const void* p) {
    return (uint32_t)__cvta_generic_to_shared(p);
}
__device__ __forceinline__ void ldsm_x4(uint32_t* r, uint32_t a) {
    asm volatile("ldmatrix.sync.aligned.m8n8.x4.shared.b16 {%0,%1,%2,%3}, [%4];"
        : "=r"(r[0]), "=r"(r[1]), "=r"(r[2]), "=r"(r[3]) : "r"(a));
}
__device__ __forceinline__ void ldsm_x2(uint32_t* r, uint32_t a) {
    asm volatile("ldmatrix.sync.aligned.m8n8.x2.shared.b16 {%0,%1}, [%2];"
        : "=r"(r[0]), "=r"(r[1]) : "r"(a));
}
__device__ __forceinline__ void ldsm_x1(uint32_t* r, uint32_t a) {
    asm volatile("ldmatrix.sync.aligned.m8n8.x1.shared.b16 {%0}, [%1];"
        : "=r"(r[0]) : "r"(a));
}
__device__ __forceinline__ void mma_f16(float* d, const uint32_t* a, const uint32_t* b) {
    asm volatile("mma.sync.aligned.m16n8k16.row.col.f32.f16.f16.f32 "
        "{%0,%1,%2,%3}, {%4,%5,%6,%7}, {%8,%9}, {%0,%1,%2,%3};"
        : "+f"(d[0]), "+f"(d[1]), "+f"(d[2]), "+f"(d[3])
        : "r"(a[0]), "r"(a[1]), "r"(a[2]), "r"(a[3]), "r"(b[0]), "r"(b[1]));
}
__device__ __forceinline__ void mma_f16_k8(float* d, const uint32_t* a, uint32_t b) {
    asm volatile("mma.sync.aligned.m16n8k8.row.col.f32.f16.f16.f32 "
        "{%0,%1,%2,%3}, {%4,%5}, {%6}, {%0,%1,%2,%3};"
        : "+f"(d[0]), "+f"(d[1]), "+f"(d[2]), "+f"(d[3])
        : "r"(a[0]), "r"(a[1]), "r"(b));
}
__device__ __forceinline__ uint32_t pack2h(__half a, __half b) {
    __half2 t; t.x = a; t.y = b;
    return *reinterpret_cast<uint32_t*>(&t);
}
__device__ __forceinline__ uint32_t pack2f(float a, float b) {
    return pack2h(__float2half_rn(a), __float2half_rn(b));
}

// ---------------------------------------------------------------- prep
__global__ void prep_kernel(
    const float* __restrict__ W1, const float* __restrict__ b1,
    const float* __restrict__ W2, const float* __restrict__ b2,
    const float* __restrict__ Wi0, const float* __restrict__ Wi1,
    const float* __restrict__ Wi2)
{
    int idx = blockIdx.x * 256 + threadIdx.x;
    if (idx < N1P * K1P) {
        int n = idx / K1P, k = idx - n * K1P;
        float v = 0.f;
        if (n < HID) {
            if (k < 530)       v = W1[(size_t)k * HID + n];
            else if (k == 530) v = b1[n];
        }
        g_w1t[idx] = __float2half_rn(v);
    }
    if (idx < OUT2 * K2P) {
        int n = idx / K2P, k = idx - n * K2P;
        float v = 0.f;
        if (k < HID)       v = W2[(size_t)k * OUT2 + n];
        else if (k == HID) v = b2[n];
        g_w2t[idx] = __float2half_rn(v);
    }
    if (idx < NIP * KIP) {
        int n = idx / KIP, k = idx - n * KIP;
        float v = 0.f;
        if (n < 8)        v = Wi0[(size_t)k * 8 + n];
        else if (n < 14)  v = Wi1[(size_t)k * 6 + (n - 8)];
        else if (n < 18)  v = Wi2[(size_t)k * 4 + (n - 14)];
        g_wit[idx] = __float2half_rn(v);
    }
}

// stage 128x64 fp32 feature chunk -> fp16 smem (stride 72 halfs)
__device__ __forceinline__ void stage_feat(
    __half* sA, const float* __restrict__ src, int row0, int c0, int tid)
{
    #pragma unroll
    for (int j = 0; j < 8; j++) {
        int i = tid + j * 256;
        int r = i >> 4, ce = (i & 15) << 2;
        float4 v = *(const float4*)(src + (size_t)(row0 + r) * FEAT + c0 + ce);
        uint2 u;
        u.x = pack2f(v.x, v.y);
        u.y = pack2f(v.z, v.w);
        *(uint2*)(sA + r * 72 + ce) = u;
    }
}
__device__ __forceinline__ void stage_b1(__half* sB, int k64, int tid)
{
    #pragma unroll
    for (int j = 0; j < 5; j++) {
        int i = tid + j * 256;                 // 144*8 = 1152 uint4
        if (i < 1152) {
            int n = i >> 3, ce = (i & 7) << 3;
            *(uint4*)(sB + n * 72 + ce) =
                *(const uint4*)(g_w1t + (size_t)n * K1P + k64 + ce);
        }
    }
}
__device__ __forceinline__ void stage_wi(__half* sW, int k64, int tid)
{
    if (tid < 192) {                           // 24*8 uint4
        int n = tid >> 3, ce = (tid & 7) << 3;
        *(uint4*)(sW + n * 72 + ce) =
            *(const uint4*)(g_wit + (size_t)n * KIP + k64 + ce);
    }
}
// special chunk (one-hot + bias-one): thread r handles row r -> race-free
__device__ __forceinline__ void stage_special(
    __half* sA, const int* __restrict__ actions, int row0, int tid)
{
    if (tid < 128) {
        int r = tid;
        #pragma unroll
        for (int q = 0; q < 8; q++)
            *(uint4*)(sA + r * 72 + q * 8) = make_uint4(0, 0, 0, 0);
        int f = (row0 + r) >> 5, ag = (row0 + r) & 31;
        int i0 = actions[(f * 3 + 0) * N_AGENTS + ag];
        int i1 = actions[(f * 3 + 1) * N_AGENTS + ag];
        int i2 = actions[(f * 3 + 2) * N_AGENTS + ag];
        __half one = __float2half_rn(1.f);
        sA[r * 72 + i0] = one;
        sA[r * 72 + 8 + i1] = one;
        sA[r * 72 + 14 + i2] = one;
        sA[r * 72 + 18] = one;                 // b1 column (k=530)
    }
}

// ---------------------------------------------------------------- FUSED ALL v2
// phase1 (double-buffered): hid-acc = [cur|onehot|1]@W1aug (kept in REGISTERS)
//                           logits  = [cur|nxt]@Wi
// phase2: agent-axis softmax
// phase3: pred = hid @ W2aug, split-k across warp pairs; hid A-fragments are
//         re-packed phase-1 accumulators (no smem round trip).
// smem layout (bytes):
//   A0 @0 (18432) | A1 @18432 (18432) | B0 @36864 (20736) | B1 @57600 (20736)
//   W0 @78336 (3456) | W1 @81792 (3456) | sL @85248 (12800)    total 98048
//   phase3 aliases: sW2 @0 (19456) | sPart @19456 (33792)
#define SA0  0
#define SA1  18432
#define SB0  36864
#define SB1O 57600
#define SW0  78336
#define SW1  81792
#define SL   85248
#define SW2O 0
#define SPRT 19456
#define SM_TOTAL 98048

__global__ __launch_bounds__(256, 2) void fused_all(
    const float* __restrict__ cur, const float* __restrict__ nxt,
    const int* __restrict__ actions, float* __restrict__ out)
{
    extern __shared__ char smem[];
    float* sL = (float*)(smem + SL);

    const int tid = threadIdx.x, lane = tid & 31, w = tid >> 5;
    const int row0 = blockIdx.x * 128;
    const int m0 = (w >> 1) * 32, n0 = (w & 1) * 72;   // gemm1 warp tile
    const int mI = w * 16;                              // inv warp rows

    // ================= phase 1 =================
    float acc1[2][9][4];
    #pragma unroll
    for (int a = 0; a < 2; a++)
        #pragma unroll
        for (int b = 0; b < 9; b++)
            #pragma unroll
            for (int c = 0; c < 4; c++) acc1[a][b][c] = 0.f;
    float accI[3][4];
    #pragma unroll
    for (int b = 0; b < 3; b++)
        #pragma unroll
        for (int c = 0; c < 4; c++) accI[b][c] = 0.f;

    // prologue: stage chunk 0 into buffer 0
    stage_feat((__half*)(smem + SA0), cur, row0, 0, tid);
    stage_b1((__half*)(smem + SB0), 0, tid);
    stage_wi((__half*)(smem + SW0), 0, tid);
    __syncthreads();

    for (int kb = 0; kb < 17; kb++) {
        __half* cA = (__half*)(smem + ((kb & 1) ? SA1 : SA0));
        __half* cB = (__half*)(smem + ((kb & 1) ? SB1O : SB0));
        __half* cW = (__half*)(smem + ((kb & 1) ? SW1 : SW0));
        const int nb = kb + 1;
        __half* nA = (__half*)(smem + ((nb & 1) ? SA1 : SA0));
        __half* nB = (__half*)(smem + ((nb & 1) ? SB1O : SB0));
        __half* nW = (__half*)(smem + ((nb & 1) ? SW1 : SW0));

        // ---- stage next chunk (overlaps with compute below)
        if (nb < 8)        stage_feat(nA, cur, row0, nb * 64, tid);
        else if (nb < 16)  stage_feat(nA, nxt, row0, (nb - 8) * 64, tid);
        else if (nb == 16) stage_special(nA, actions, row0, tid);
        if (nb < 8)        stage_b1(nB, nb * 64, tid);
        else if (nb == 16) stage_b1(nB, 512, tid);
        if (nb < 16)       stage_wi(nW, nb * 64, tid);

        // ---- compute current chunk
        const bool g1 = (kb < 8) || (kb == 16);
        const bool iv = (kb < 16);
        const int kmax = (kb == 16) ? 2 : 4;
        for (int ks = 0; ks < kmax; ks++) {
            int k0 = ks * 16;
            if (g1) {
                uint32_t a[2][4];
                #pragma unroll
                for (int mt = 0; mt < 2; mt++) {
                    int r = m0 + mt * 16 + (lane & 15);
                    int c = k0 + ((lane >> 4) << 3);
                    ldsm_x4(a[mt], smaddr(cA + r * 72 + c));
                }
                #pragma unroll
                for (int nt = 0; nt < 9; nt++) {
                    uint32_t b[2];
                    int l15 = lane & 15;
                    int nr = n0 + nt * 8 + (l15 & 7);
                    int c = k0 + ((l15 >> 3) << 3);
                    ldsm_x2(b, smaddr(cB + nr * 72 + c));
                    #pragma unroll
                    for (int mt = 0; mt < 2; mt++)
                        mma_f16(acc1[mt][nt], a[mt], b);
                }
            }
            if (iv) {
                uint32_t ai[4];
                {
                    int r = mI + (lane & 15);
                    int c = k0 + ((lane >> 4) << 3);
                    ldsm_x4(ai, smaddr(cA + r * 72 + c));
                }
                #pragma unroll
                for (int nt = 0; nt < 3; nt++) {
                    uint32_t b[2];
                    int l15 = lane & 15;
                    int nr = nt * 8 + (l15 & 7);
                    int c = k0 + ((l15 >> 3) << 3);
                    ldsm_x2(b, smaddr(cW + nr * 72 + c));
                    mma_f16(accI[nt], ai, b);
                }
            }
        }
        __syncthreads();
    }

    // ================= phase 2: logits + softmax =================
    #pragma unroll
    for (int nt = 0; nt < 3; nt++) {
        int col = nt * 8 + ((lane & 3) << 1);
        int rl = mI + (lane >> 2);
        sL[rl * 25 + col]           = accI[nt][0];
        sL[rl * 25 + col + 1]       = accI[nt][1];
        sL[(rl + 8) * 25 + col]     = accI[nt][2];
        sL[(rl + 8) * 25 + col + 1] = accI[nt][3];
    }

    // convert hid accumulators -> phase-3 A fragments (registers only).
    // warp n-range [n0, n0+72) becomes its k-range in the split-k gemm2.
    // C-frag (c0..c3) of an 8-col tile == A-frag halves of the same k8 block.
    if (n0 == 72 && (lane & 3) == 2) {     // global col 140: ones column (b2)
        acc1[0][8][0] = 1.f; acc1[0][8][2] = 1.f;
        acc1[1][8][0] = 1.f; acc1[1][8][2] = 1.f;
    }
    uint32_t hf[2][4][4], hf8[2][2];
    #pragma unroll
    for (int mt = 0; mt < 2; mt++) {
        #pragma unroll
        for (int kt = 0; kt < 4; kt++) {
            hf[mt][kt][0] = pack2f(acc1[mt][2 * kt][0],     acc1[mt][2 * kt][1]);
            hf[mt][kt][1] = pack2f(acc1[mt][2 * kt][2],     acc1[mt][2 * kt][3]);
            hf[mt][kt][2] = pack2f(acc1[mt][2 * kt + 1][0], acc1[mt][2 * kt + 1][1]);
            hf[mt][kt][3] = pack2f(acc1[mt][2 * kt + 1][2], acc1[mt][2 * kt + 1][3]);
        }
        hf8[mt][0] = pack2f(acc1[mt][8][0], acc1[mt][8][1]);
        hf8[mt][1] = pack2f(acc1[mt][8][2], acc1[mt][8][3]);
    }
    __syncthreads();

    // softmax over 32 agents, per frame (4 frames), per logit column
    if (tid < 72) {
        int f = tid / 18, j = tid - f * 18;
        float vals[32], mx = -1e30f;
        #pragma unroll
        for (int a = 0; a < 32; a++) {
            vals[a] = sL[(f * 32 + a) * 25 + j];
            mx = fmaxf(mx, vals[a]);
        }
        float s = 0.f;
        #pragma unroll
        for (int a = 0; a < 32; a++) { vals[a] = expf(vals[a] - mx); s += vals[a]; }
        float inv = 1.f / s;
        int frame = blockIdx.x * 4 + f;
        if (j < 8) {
            size_t base = OFF_A0 + (size_t)(frame * 32) * 8 + j;
            #pragma unroll
            for (int a = 0; a < 32; a++) out[base + (size_t)a * 8] = vals[a] * inv;
        } else if (j < 14) {
            size_t base = OFF_A1 + (size_t)(frame * 32) * 6 + (j - 8);
            #pragma unroll
            for (int a = 0; a < 32; a++) out[base + (size_t)a * 6] = vals[a] * inv;
        } else {
            size_t base = OFF_A2 + (size_t)(frame * 32) * 4 + (j - 14);
            #pragma unroll
            for (int a = 0; a < 32; a++) out[base + (size_t)a * 4] = vals[a] * inv;
        }
    }
    __syncthreads();   // sL dead; phase-1 buffers dead

    // ================= phase 3: split-k gemm2 from registers =================
    __half* sW2  = (__half*)(smem + SW2O);
    float*  sPrt = (float*)(smem + SPRT);

    for (int c = 0; c < 4; c++) {
        // stage W2 chunk: 64 n-rows x 144 k (stride 152)
        #pragma unroll
        for (int j = 0; j < 5; j++) {
            int i = tid + j * 256;
            if (i < 1152) {
                int n = i / 18, t = i - n * 18;
                *(uint4*)(sW2 + n * 152 + t * 8) =
                    *(const uint4*)(g_w2t + (size_t)(c * 64 + n) * K2P + t * 8);
            }
        }
        __syncthreads();

        float acc3[2][8][4];
        #pragma unroll
        for (int a = 0; a < 2; a++)
            #pragma unroll
            for (int b = 0; b < 8; b++)
                #pragma unroll
                for (int q = 0; q < 4; q++) acc3[a][b][q] = 0.f;

        #pragma unroll
        for (int nt2 = 0; nt2 < 8; nt2++) {
            #pragma unroll
            for (int kt = 0; kt < 4; kt++) {
                uint32_t b[2];
                int l15 = lane & 15;
                ldsm_x2(b, smaddr(sW2 + (nt2 * 8 + (l15 & 7)) * 152
                                  + n0 + kt * 16 + ((l15 >> 3) << 3)));
                mma_f16(acc3[0][nt2], hf[0][kt], b);
                mma_f16(acc3[1][nt2], hf[1][kt], b);
            }
            uint32_t b1r;
            ldsm_x1(&b1r, smaddr(sW2 + (nt2 * 8 + (lane & 7)) * 152 + n0 + 64));
            mma_f16_k8(acc3[0][nt2], hf8[0], b1r);
            mma_f16_k8(acc3[1][nt2], hf8[1], b1r);
        }

        // odd warps (k-half 72..143) write partials
        if (w & 1) {
            float* base = sPrt + (w >> 1) * 2112;   // 32 rows, stride 66
            #pragma unroll
            for (int mt = 0; mt < 2; mt++)
                #pragma unroll
                for (int nt2 = 0; nt2 < 8; nt2++) {
                    int rl = mt * 16 + (lane >> 2);
                    int cp = nt2 * 8 + ((lane & 3) << 1);
                    *(float2*)(base + rl * 66 + cp) =
                        make_float2(acc3[mt][nt2][0], acc3[mt][nt2][1]);
                    *(float2*)(base + (rl + 8) * 66 + cp) =
                        make_float2(acc3[mt][nt2][2], acc3[mt][nt2][3]);
                }
        }
        __syncthreads();
        // even warps (k-half 0..71) reduce + store
        if (!(w & 1)) {
            float* base = sPrt + (w >> 1) * 2112;
            #pragma unroll
            for (int mt = 0; mt < 2; mt++)
                #pragma unroll
                for (int nt2 = 0; nt2 < 8; nt2++) {
                    int rl = mt * 16 + (lane >> 2);
                    int cp = nt2 * 8 + ((lane & 3) << 1);
                    float2 p0 = *(float2*)(base + rl * 66 + cp);
                    float2 p1 = *(float2*)(base + (rl + 8) * 66 + cp);
                    int row = row0 + m0 + mt * 16 + (lane >> 2);
                    int col = c * 64 + cp;
                    *(float2*)(out + (size_t)row * OUT2 + col) =
                        make_float2(acc3[mt][nt2][0] + p0.x, acc3[mt][nt2][1] + p0.y);
                    *(float2*)(out + (size_t)(row + 8) * OUT2 + col) =
                        make_float2(acc3[mt][nt2][2] + p1.x, acc3[mt][nt2][3] + p1.y);
                }
        }
        __syncthreads();
    }
}

// ----------------------------------------------------------------
extern "C" void kernel_launch(void* const* d_in, const int* in_sizes, int n_in,
                              void* d_out, int out_size)
{
    const float* cur  = (const float*)d_in[0];
    const float* nxt  = (const float*)d_in[1];
    const int*   acts = (const int*)  d_in[2];
    const float* W1   = (const float*)d_in[3];
    const float* b1   = (const float*)d_in[4];
    const float* W2   = (const float*)d_in[5];
    const float* b2   = (const float*)d_in[6];
    const float* Wi0  = (const float*)d_in[7];
    const float* Wi1  = (const float*)d_in[9];
    const float* Wi2  = (const float*)d_in[11];
    float* out = (float*)d_out;

    cudaFuncSetAttribute(fused_all, cudaFuncAttributeMaxDynamicSharedMemorySize, SM_TOTAL);

    prep_kernel<<<(N1P * K1P + 255) / 256, 256>>>(W1, b1, W2, b2, Wi0, Wi1, Wi2);
    fused_all<<<N_ROWS / 128, 256, SM_TOTAL>>>(cur, nxt, acts, out);
}

// round 8
// speedup vs baseline: 1.0926x; 1.0926x over previous
#include <cuda_runtime.h>
#include <cuda_fp16.h>
#include <stdint.h>
#include <math.h>

#define N_FRAMES 2048
#define N_AGENTS 32
#define N_ROWS 65536
#define FEAT 512
#define HID 140
#define OUT2 256

#define OFF_A0 (N_ROWS * OUT2)
#define OFF_A1 (OFF_A0 + N_ROWS * 8)
#define OFF_A2 (OFF_A1 + N_ROWS * 6)

// padded dims
#define K1P 576   // 512 feat + 18 onehot + bias@530 + pad
#define N1P 144   // 140 hid + ones@140 + pad
#define K2P 144
#define KIP 1024  // cur|next
#define NIP 24

// single-fp16 transposed weights
__device__ __align__(16) __half g_w1t[N1P * K1P];     // [n][k]
__device__ __align__(16) __half g_wit[NIP * KIP];     // [n][k]
__device__ __align__(16) __half g_w2t[OUT2 * K2P];    // [n][k]

// ---------------------------------------------------------------- helpers
__device__ __forceinline__ uint32_t smaddr(const void* p) {
    return (uint32_t)__cvta_generic_to_shared(p);
}
__device__ __forceinline__ void ldsm_x4(uint32_t* r, uint32_t a) {
    asm volatile("ldmatrix.sync.aligned.m8n8.x4.shared.b16 {%0,%1,%2,%3}, [%4];"
        : "=r"(r[0]), "=r"(r[1]), "=r"(r[2]), "=r"(r[3]) : "r"(a));
}
__device__ __forceinline__ void ldsm_x2(uint32_t* r, uint32_t a) {
    asm volatile("ldmatrix.sync.aligned.m8n8.x2.shared.b16 {%0,%1}, [%2];"
        : "=r"(r[0]), "=r"(r[1]) : "r"(a));
}
__device__ __forceinline__ void mma_f16(float* d, const uint32_t* a, const uint32_t* b) {
    asm volatile("mma.sync.aligned.m16n8k16.row.col.f32.f16.f16.f32 "
        "{%0,%1,%2,%3}, {%4,%5,%6,%7}, {%8,%9}, {%0,%1,%2,%3};"
        : "+f"(d[0]), "+f"(d[1]), "+f"(d[2]), "+f"(d[3])
        : "r"(a[0]), "r"(a[1]), "r"(a[2]), "r"(a[3]), "r"(b[0]), "r"(b[1]));
}
__device__ __forceinline__ uint32_t pack2h(__half a, __half b) {
    __half2 t; t.x = a; t.y = b;
    return *reinterpret_cast<uint32_t*>(&t);
}
__device__ __forceinline__ uint32_t pack2f(float a, float b) {
    return pack2h(__float2half_rn(a), __float2half_rn(b));
}

// ---------------------------------------------------------------- prep
__global__ void prep_kernel(
    const float* __restrict__ W1, const float* __restrict__ b1,
    const float* __restrict__ W2, const float* __restrict__ b2,
    const float* __restrict__ Wi0, const float* __restrict__ Wi1,
    const float* __restrict__ Wi2)
{
    int idx = blockIdx.x * 256 + threadIdx.x;
    if (idx < N1P * K1P) {
        int n = idx / K1P, k = idx - n * K1P;
        float v = 0.f;
        if (n < HID) {
            if (k < 530)       v = W1[(size_t)k * HID + n];
            else if (k == 530) v = b1[n];
        }
        g_w1t[idx] = __float2half_rn(v);
    }
    if (idx < OUT2 * K2P) {
        int n = idx / K2P, k = idx - n * K2P;
        float v = 0.f;
        if (k < HID)       v = W2[(size_t)k * OUT2 + n];
        else if (k == HID) v = b2[n];
        g_w2t[idx] = __float2half_rn(v);
    }
    if (idx < NIP * KIP) {
        int n = idx / KIP, k = idx - n * KIP;
        float v = 0.f;
        if (n < 8)        v = Wi0[(size_t)k * 8 + n];
        else if (n < 14)  v = Wi1[(size_t)k * 6 + (n - 8)];
        else if (n < 18)  v = Wi2[(size_t)k * 4 + (n - 14)];
        g_wit[idx] = __float2half_rn(v);
    }
}

// stage 128x64 fp32 feature chunk -> fp16 smem (stride 72 halfs)
__device__ __forceinline__ void stage_feat(
    __half* sA, const float* __restrict__ src, int row0, int c0, int tid)
{
    #pragma unroll
    for (int j = 0; j < 8; j++) {
        int i = tid + j * 256;
        int r = i >> 4, ce = (i & 15) << 2;
        float4 v = *(const float4*)(src + (size_t)(row0 + r) * FEAT + c0 + ce);
        uint2 u;
        u.x = pack2f(v.x, v.y);
        u.y = pack2f(v.z, v.w);
        *(uint2*)(sA + r * 72 + ce) = u;
    }
}
__device__ __forceinline__ void stage_b1(__half* sB, int k64, int tid)
{
    #pragma unroll
    for (int j = 0; j < 5; j++) {
        int i = tid + j * 256;                 // 144*8 = 1152 uint4
        if (i < 1152) {
            int n = i >> 3, ce = (i & 7) << 3;
            *(uint4*)(sB + n * 72 + ce) =
                *(const uint4*)(g_w1t + (size_t)n * K1P + k64 + ce);
        }
    }
}
__device__ __forceinline__ void stage_wi(__half* sW, int k64, int tid)
{
    if (tid < 192) {                           // 24*8 uint4
        int n = tid >> 3, ce = (tid & 7) << 3;
        *(uint4*)(sW + n * 72 + ce) =
            *(const uint4*)(g_wit + (size_t)n * KIP + k64 + ce);
    }
}
// special chunk (one-hot + bias-one): thread r handles row r -> race-free
__device__ __forceinline__ void stage_special(
    __half* sA, const int* __restrict__ actions, int row0, int tid)
{
    if (tid < 128) {
        int r = tid;
        #pragma unroll
        for (int q = 0; q < 8; q++)
            *(uint4*)(sA + r * 72 + q * 8) = make_uint4(0, 0, 0, 0);
        int f = (row0 + r) >> 5, ag = (row0 + r) & 31;
        int i0 = actions[(f * 3 + 0) * N_AGENTS + ag];
        int i1 = actions[(f * 3 + 1) * N_AGENTS + ag];
        int i2 = actions[(f * 3 + 2) * N_AGENTS + ag];
        __half one = __float2half_rn(1.f);
        sA[r * 72 + i0] = one;
        sA[r * 72 + 8 + i1] = one;
        sA[r * 72 + 14 + i2] = one;
        sA[r * 72 + 18] = one;                 // b1 column (k=530)
    }
}
// stage W2 chunk: 64 n-rows x 144 k (stride 152)
__device__ __forceinline__ void stage_w2(__half* sW2, int c, int tid)
{
    #pragma unroll
    for (int j = 0; j < 5; j++) {
        int i = tid + j * 256;
        if (i < 1152) {
            int n = i / 18, t = i - n * 18;
            *(uint4*)(sW2 + n * 152 + t * 8) =
                *(const uint4*)(g_w2t + (size_t)(c * 64 + n) * K2P + t * 8);
        }
    }
}

// ---------------------------------------------------------------- FUSED ALL v3
// phase1 (double-buffered, 1 sync/chunk): hid = [cur|onehot|1]@W1aug,
//        logits = [cur|nxt]@Wi; inv reuses gemm1's A fragments on cur chunks.
// phase2: hid -> smem fp16 (R6 style), logits -> smem, agent softmax.
// phase3: pred = hid(smem) @ W2aug, W2 chunks double-buffered.
// smem phase1 (bytes):
//   A0 @0 18432 | A1 @18432 | B0 @36864 20736 | B1 @57600 20736
//   W0 @78336 3456 | W1 @81792 3456 | sL @85248 12800    total 98048
// phase2/3 aliases (phase-1 staging dead):
//   sHid @0 38912 | sW2 bufs @40960 / @61440 (19456 each)
#define SA0  0
#define SA1  18432
#define SB0  36864
#define SB1O 57600
#define SW0  78336
#define SW1  81792
#define SL   85248
#define SHID 0
#define SW2A 40960
#define SW2B 61440
#define SM_TOTAL 98048

__global__ __launch_bounds__(256, 2) void fused_all(
    const float* __restrict__ cur, const float* __restrict__ nxt,
    const int* __restrict__ actions, float* __restrict__ out)
{
    extern __shared__ char smem[];
    float* sL = (float*)(smem + SL);

    const int tid = threadIdx.x, lane = tid & 31, w = tid >> 5;
    const int row0 = blockIdx.x * 128;
    const int m0 = (w >> 1) * 32, n0 = (w & 1) * 72;   // gemm1 warp tile
    const int mI = w * 16;                              // inv warp rows (== m0 + (w&1)*16)
    const int wodd = w & 1;

    // ================= phase 1 =================
    float acc1[2][9][4];
    #pragma unroll
    for (int a = 0; a < 2; a++)
        #pragma unroll
        for (int b = 0; b < 9; b++)
            #pragma unroll
            for (int c = 0; c < 4; c++) acc1[a][b][c] = 0.f;
    float accI[3][4];
    #pragma unroll
    for (int b = 0; b < 3; b++)
        #pragma unroll
        for (int c = 0; c < 4; c++) accI[b][c] = 0.f;

    // prologue: stage chunk 0 into buffer 0
    stage_feat((__half*)(smem + SA0), cur, row0, 0, tid);
    stage_b1((__half*)(smem + SB0), 0, tid);
    stage_wi((__half*)(smem + SW0), 0, tid);
    __syncthreads();

    for (int kb = 0; kb < 17; kb++) {
        __half* cA = (__half*)(smem + ((kb & 1) ? SA1 : SA0));
        __half* cB = (__half*)(smem + ((kb & 1) ? SB1O : SB0));
        __half* cW = (__half*)(smem + ((kb & 1) ? SW1 : SW0));
        const int nb = kb + 1;
        __half* nA = (__half*)(smem + ((nb & 1) ? SA1 : SA0));
        __half* nB = (__half*)(smem + ((nb & 1) ? SB1O : SB0));
        __half* nW = (__half*)(smem + ((nb & 1) ? SW1 : SW0));

        // ---- stage next chunk (writes the other buffer; overlaps compute)
        if (nb < 8)        stage_feat(nA, cur, row0, nb * 64, tid);
        else if (nb < 16)  stage_feat(nA, nxt, row0, (nb - 8) * 64, tid);
        else if (nb == 16) stage_special(nA, actions, row0, tid);
        if (nb < 8)        stage_b1(nB, nb * 64, tid);
        else if (nb == 16) stage_b1(nB, 512, tid);
        if (nb < 16)       stage_wi(nW, nb * 64, tid);

        // ---- compute current chunk
        const bool g1 = (kb < 8) || (kb == 16);
        const bool iv = (kb < 16);
        const int kmax = (kb == 16) ? 2 : 4;
        for (int ks = 0; ks < kmax; ks++) {
            int k0 = ks * 16;
            uint32_t ai[4];
            if (g1) {
                uint32_t a[2][4];
                #pragma unroll
                for (int mt = 0; mt < 2; mt++) {
                    int r = m0 + mt * 16 + (lane & 15);
                    int c = k0 + ((lane >> 4) << 3);
                    ldsm_x4(a[mt], smaddr(cA + r * 72 + c));
                }
                #pragma unroll
                for (int nt = 0; nt < 9; nt++) {
                    uint32_t b[2];
                    int l15 = lane & 15;
                    int nr = n0 + nt * 8 + (l15 & 7);
                    int c = k0 + ((l15 >> 3) << 3);
                    ldsm_x2(b, smaddr(cB + nr * 72 + c));
                    #pragma unroll
                    for (int mt = 0; mt < 2; mt++)
                        mma_f16(acc1[mt][nt], a[mt], b);
                }
                // inv reuses gemm1's A fragment for this warp's inv rows
                #pragma unroll
                for (int q = 0; q < 4; q++)
                    ai[q] = wodd ? a[1][q] : a[0][q];
            } else if (iv) {
                int r = mI + (lane & 15);
                int c = k0 + ((lane >> 4) << 3);
                ldsm_x4(ai, smaddr(cA + r * 72 + c));
            }
            if (iv) {
                #pragma unroll
                for (int nt = 0; nt < 3; nt++) {
                    uint32_t b[2];
                    int l15 = lane & 15;
                    int nr = nt * 8 + (l15 & 7);
                    int c = k0 + ((l15 >> 3) << 3);
                    ldsm_x2(b, smaddr(cW + nr * 72 + c));
                    mma_f16(accI[nt], ai, b);
                }
            }
        }
        __syncthreads();
    }

    // ================= phase 2: hid -> smem, logits -> smem, softmax ==========
    __half* sHid = (__half*)(smem + SHID);
    #pragma unroll
    for (int mt = 0; mt < 2; mt++) {
        #pragma unroll
        for (int nt = 0; nt < 9; nt++) {
            int col = n0 + nt * 8 + ((lane & 3) << 1);
            int rl = m0 + mt * 16 + (lane >> 2);
            #pragma unroll
            for (int h = 0; h < 2; h++) {
                float v0 = acc1[mt][nt][h * 2 + 0];
                float v1 = acc1[mt][nt][h * 2 + 1];
                if (col == 140) v0 = 1.f;
                *(uint32_t*)(sHid + (rl + h * 8) * 152 + col) =
                    pack2h(__float2half_rn(v0), __float2half_rn(v1));
            }
        }
    }
    #pragma unroll
    for (int nt = 0; nt < 3; nt++) {
        int col = nt * 8 + ((lane & 3) << 1);
        int rl = mI + (lane >> 2);
        sL[rl * 25 + col]           = accI[nt][0];
        sL[rl * 25 + col + 1]       = accI[nt][1];
        sL[(rl + 8) * 25 + col]     = accI[nt][2];
        sL[(rl + 8) * 25 + col + 1] = accI[nt][3];
    }
    __syncthreads();

    // stage W2 chunk 0 (overlaps with softmax below)
    stage_w2((__half*)(smem + SW2A), 0, tid);

    // softmax over 32 agents, per frame (4 frames), per logit column
    if (tid < 72) {
        int f = tid / 18, j = tid - f * 18;
        float vals[32], mx = -1e30f;
        #pragma unroll
        for (int a = 0; a < 32; a++) {
            vals[a] = sL[(f * 32 + a) * 25 + j];
            mx = fmaxf(mx, vals[a]);
        }
        float s = 0.f;
        #pragma unroll
        for (int a = 0; a < 32; a++) { vals[a] = expf(vals[a] - mx); s += vals[a]; }
        float inv = 1.f / s;
        int frame = blockIdx.x * 4 + f;
        if (j < 8) {
            size_t base = OFF_A0 + (size_t)(frame * 32) * 8 + j;
            #pragma unroll
            for (int a = 0; a < 32; a++) out[base + (size_t)a * 8] = vals[a] * inv;
        } else if (j < 14) {
            size_t base = OFF_A1 + (size_t)(frame * 32) * 6 + (j - 8);
            #pragma unroll
            for (int a = 0; a < 32; a++) out[base + (size_t)a * 6] = vals[a] * inv;
        } else {
            size_t base = OFF_A2 + (size_t)(frame * 32) * 4 + (j - 14);
            #pragma unroll
            for (int a = 0; a < 32; a++) out[base + (size_t)a * 4] = vals[a] * inv;
        }
    }
    __syncthreads();

    // ================= phase 3: gemm2 from smem hid (W2 double-buffered) =====
    const int m2 = (w >> 1) * 32, n2 = (w & 1) * 32;
    for (int c = 0; c < 4; c++) {
        __half* cW2 = (__half*)(smem + ((c & 1) ? SW2B : SW2A));
        if (c < 3) stage_w2((__half*)(smem + (((c + 1) & 1) ? SW2B : SW2A)), c + 1, tid);

        float acc[2][4][4];
        #pragma unroll
        for (int a = 0; a < 2; a++)
            #pragma unroll
            for (int b = 0; b < 4; b++)
                #pragma unroll
                for (int q = 0; q < 4; q++) acc[a][b][q] = 0.f;

        #pragma unroll
        for (int ks = 0; ks < 9; ks++) {
            int k0 = ks * 16;
            uint32_t a[2][4];
            #pragma unroll
            for (int mt = 0; mt < 2; mt++) {
                int r = m2 + mt * 16 + (lane & 15);
                int kc = k0 + ((lane >> 4) << 3);
                ldsm_x4(a[mt], smaddr(sHid + r * 152 + kc));
            }
            #pragma unroll
            for (int nt = 0; nt < 4; nt++) {
                uint32_t b[2];
                int l15 = lane & 15;
                int nr = n2 + nt * 8 + (l15 & 7);
                int kc = k0 + ((l15 >> 3) << 3);
                ldsm_x2(b, smaddr(cW2 + nr * 152 + kc));
                #pragma unroll
                for (int mt = 0; mt < 2; mt++)
                    mma_f16(acc[mt][nt], a[mt], b);
            }
        }

        #pragma unroll
        for (int mt = 0; mt < 2; mt++) {
            #pragma unroll
            for (int nt = 0; nt < 4; nt++) {
                int col = c * 64 + n2 + nt * 8 + ((lane & 3) << 1);
                int rb = row0 + m2 + mt * 16 + (lane >> 2);
                *(float2*)(out + (size_t)rb * OUT2 + col) =
                    make_float2(acc[mt][nt][0], acc[mt][nt][1]);
                *(float2*)(out + (size_t)(rb + 8) * OUT2 + col) =
                    make_float2(acc[mt][nt][2], acc[mt][nt][3]);
            }
        }
        __syncthreads();
    }
}

// ----------------------------------------------------------------
extern "C" void kernel_launch(void* const* d_in, const int* in_sizes, int n_in,
                              void* d_out, int out_size)
{
    const float* cur  = (const float*)d_in[0];
    const float* nxt  = (const float*)d_in[1];
    const int*   acts = (const int*)  d_in[2];
    const float* W1   = (const float*)d_in[3];
    const float* b1   = (const float*)d_in[4];
    const float* W2   = (const float*)d_in[5];
    const float* b2   = (const float*)d_in[6];
    const float* Wi0  = (const float*)d_in[7];
    const float* Wi1  = (const float*)d_in[9];
    const float* Wi2  = (const float*)d_in[11];
    float* out = (float*)d_out;

    cudaFuncSetAttribute(fused_all, cudaFuncAttributeMaxDynamicSharedMemorySize, SM_TOTAL);

    prep_kernel<<<(N1P * K1P + 255) / 256, 256>>>(W1, b1, W2, b2, Wi0, Wi1, Wi2);
    fused_all<<<N_ROWS / 128, 256, SM_TOTAL>>>(cur, nxt, acts, out);
}